// round 7
// baseline (speedup 1.0000x reference)
#include <cuda_runtime.h>
#include <cuda_pipeline.h>
#include <math.h>

#define D_ 1024
#define H_ 8
#define F_ 4096

#define NS 5          // pipeline stages
#define CHUNK 256     // floats per row per stage (1KB)
#define NCHUNK 4      // chunks per row (D_/CHUNK)
#define TROWS 32      // rows per tile (8 warps x 4 rows)
#define STAGE_FLOATS (TROWS * CHUNK)   // 8192 floats = 32KB
#define TILE_ 32      // rows per filter block

// Scratch: keys [b][f][h] (64B per row), thresholds per (b,h).
__device__ unsigned long long g_keys[8 * 4096 * 8];
__device__ unsigned long long g_thr[64];

__device__ __forceinline__ unsigned int f2ord(float f) {
    unsigned int u = __float_as_uint(f);
    return (u & 0x80000000u) ? ~u : (u | 0x80000000u);
}
__device__ __forceinline__ unsigned long long pack2(float lo, float hi) {
    unsigned long long p;
    asm("mov.b64 %0, {%1, %2};" : "=l"(p) : "f"(lo), "f"(hi));
    return p;
}
__device__ __forceinline__ void unpack2(unsigned long long p, float& lo, float& hi) {
    asm("mov.b64 {%0, %1}, %2;" : "=f"(lo), "=f"(hi) : "l"(p));
}
#define FMA2(acc, a, b) \
    asm("fma.rn.f32x2 %0, %1, %2, %0;" : "+l"(acc) : "l"(a), "l"(b))
#define ADD2(acc, a) \
    asm("add.rn.f32x2 %0, %0, %1;" : "+l"(acc) : "l"(a))

// ---------------------------------------------------------------------------
// Kernel 1: cp.async 5-stage pipelined score. Stage = 32 rows x 1KB d-chunk.
// Warps compute 4 rows each from smem with FFMA2; accs persist across the
// 4 chunks of a tile; packed butterfly reduce at tile end.
// ---------------------------------------------------------------------------
__global__ void __launch_bounds__(256, 1) score_kernel(
    const float* __restrict__ x,
    const float* __restrict__ W,      // [D, H]
    const float* __restrict__ bias,   // [H]
    int nrows)
{
    extern __shared__ float smem[];
    float* Wt  = smem;                 // [h*D_ + d], 32KB
    float* stg = smem + H_ * D_;       // NS stages of 32KB

    const int tid  = threadIdx.x;
    const int warp = tid >> 5;
    const int lane = tid & 31;
    const int bid  = blockIdx.x;
    const int grid = gridDim.x;

    for (int i = tid; i < D_ * H_; i += 256) {
        int d = i >> 3, h = i & 7;
        Wt[h * D_ + d] = W[i];
    }
    __syncthreads();

    const int ntiles = nrows / TROWS;
    const int nt_mine = (ntiles > bid) ? ((ntiles - bid + grid - 1) / grid) : 0;
    const int total_m = nt_mine * NCHUNK;
    if (total_m == 0) return;

    // --- prologue: commit NS-1 groups (empty if past the end) ---
    for (int m = 0; m < NS - 1; m++) {
        if (m < total_m) {
            const int tile = bid + (m >> 2) * grid;
            const int c = m & 3;
            const float* src = x + (size_t)tile * TROWS * D_ + c * CHUNK;
            float* dst = stg + (m % NS) * STAGE_FLOATS;
            for (int i = tid; i < TROWS * 64; i += 256) {
                int r = i >> 6, seg = i & 63;
                __pipeline_memcpy_async(dst + r * CHUNK + seg * 4,
                                        src + (size_t)r * D_ + seg * 4, 16);
            }
        }
        __pipeline_commit();
    }

    const int r0 = warp * 4;
    const unsigned long long ABS2 = 0x7FFFFFFF7FFFFFFFull;
    unsigned long long acc2[4][H_];

    for (int m = 0; m < total_m; m++) {
        const int c = m & 3;
        const int tile = bid + (m >> 2) * grid;

        __pipeline_wait_prior(NS - 2);   // group m complete (one commit/iter)
        __syncthreads();                 // cross-thread visibility

        if (c == 0) {
#pragma unroll
            for (int r = 0; r < 4; r++)
#pragma unroll
                for (int h = 0; h < H_; h++) acc2[r][h] = 0ull;
        }

        const float4* slot = (const float4*)(stg + (m % NS) * STAGE_FLOATS);
#pragma unroll
        for (int j2 = 0; j2 < 2; j2++) {
            const int d4l = lane + 32 * j2;          // 0..63 within chunk
            unsigned long long axy[4], azw[4];
#pragma unroll
            for (int r = 0; r < 4; r++) {
                float4 v = slot[(r0 + r) * (CHUNK / 4) + d4l];
                axy[r] = pack2(v.x, v.y) & ABS2;
                azw[r] = pack2(v.z, v.w) & ABS2;
            }
            const int dg = c * CHUNK + 4 * d4l;
#pragma unroll
            for (int h = 0; h < H_; h++) {
                const ulonglong2 wv = *(const ulonglong2*)&Wt[h * D_ + dg];
#pragma unroll
                for (int r = 0; r < 4; r++) {
                    FMA2(acc2[r][h], axy[r], wv.x);
                    FMA2(acc2[r][h], azw[r], wv.y);
                }
            }
        }

        if (c == NCHUNK - 1) {
            // packed butterfly reduce across lanes
#pragma unroll
            for (int off = 16; off; off >>= 1) {
#pragma unroll
                for (int r = 0; r < 4; r++)
#pragma unroll
                    for (int h = 0; h < H_; h++) {
                        unsigned long long p = acc2[r][h];
                        unsigned int lo = __shfl_xor_sync(0xffffffffu, (unsigned int)p, off);
                        unsigned int hi = __shfl_xor_sync(0xffffffffu, (unsigned int)(p >> 32), off);
                        unsigned long long q = ((unsigned long long)hi << 32) | lo;
                        ADD2(acc2[r][h], q);
                    }
            }
            if (lane < 4) {
                const int r = lane;
                const int row = tile * TROWS + r0 + r;
                const int b = row / F_;
                const int f = row - b * F_;
                const unsigned int finv = 0xFFFFFFFFu - (unsigned int)f;
                unsigned long long* kout = g_keys + (size_t)row * H_;
#pragma unroll
                for (int h = 0; h < H_; h++) {
                    float lo, hi;
                    unpack2(acc2[r][h], lo, hi);
                    float s = lo + hi + bias[h];
                    kout[h] = ((unsigned long long)f2ord(s) << 32) | (unsigned long long)finv;
                }
            }
        }
        __syncthreads();                 // all done reading slot m%NS

        // issue group m+NS-1 into the slot just freed
        {
            const int mi = m + NS - 1;
            if (mi < total_m) {
                const int tile2 = bid + (mi >> 2) * grid;
                const int c2 = mi & 3;
                const float* src = x + (size_t)tile2 * TROWS * D_ + c2 * CHUNK;
                float* dst = stg + (mi % NS) * STAGE_FLOATS;
                for (int i = tid; i < TROWS * 64; i += 256) {
                    int r = i >> 6, seg = i & 63;
                    __pipeline_memcpy_async(dst + r * CHUNK + seg * 4,
                                            src + (size_t)r * D_ + seg * 4, 16);
                }
            }
            __pipeline_commit();
        }
    }
}

// ---------------------------------------------------------------------------
// Kernel 2: per (b,h) exact radix-select, 4-way split histograms to cut
// smem-atomic serialization.
// ---------------------------------------------------------------------------
__global__ void __launch_bounds__(1024) topk_kernel(
    const float* __restrict__ sparsity_offset)
{
    __shared__ unsigned long long s[F_];   // 32 KB
    __shared__ int hist[4][256];           // 4 KB
    __shared__ int sh_bin, sh_need;

    const int bh = blockIdx.x;
    const int b  = bh >> 3;
    const int h  = bh & (H_ - 1);
    const int t  = threadIdx.x;
    const int lane = t & 31;
    const int wg4 = (t >> 5) & 3;

#pragma unroll
    for (int j = 0; j < 4; j++) {
        int i = t + j * 1024;
        s[i] = g_keys[((size_t)b * F_ + i) * H_ + h];
    }

    if (t == 0) {
        double off = (double)sparsity_offset[h];
        double sp  = 1.0 / (1.0 + exp(-off)) * 0.3 + 0.15;
        int k = (int)((double)F_ * sp);     // trunc, matches numpy int()
        if (k < 1)  k = 1;
        if (k > F_) k = F_;
        sh_need = k;
    }
    __syncthreads();

    unsigned long long prefix = 0ull, pmask = 0ull;

    for (int shift = 56; shift >= 0; shift -= 8) {
        if (t < 256) { hist[0][t] = 0; hist[1][t] = 0; hist[2][t] = 0; hist[3][t] = 0; }
        __syncthreads();
#pragma unroll
        for (int j = 0; j < 4; j++) {
            unsigned long long key = s[t + j * 1024];
            if ((key & pmask) == prefix)
                atomicAdd(&hist[wg4][(int)((key >> shift) & 255ull)], 1);
        }
        __syncthreads();

        if (t < 32) {
            int c[8], lsum = 0;
#pragma unroll
            for (int q = 0; q < 8; q++) {
                int bin = lane * 8 + q;
                c[q] = hist[0][bin] + hist[1][bin] + hist[2][bin] + hist[3][bin];
                lsum += c[q];
            }
            int ssum = lsum;
#pragma unroll
            for (int off = 1; off < 32; off <<= 1) {
                int o = __shfl_down_sync(0xffffffffu, ssum, off);
                if (lane + off < 32) ssum += o;
            }
            int above = ssum - lsum;
            int need = sh_need;
            int cum = above;
#pragma unroll
            for (int q = 7; q >= 0; q--) {
                int bin = lane * 8 + q;
                if (cum < need && need <= cum + c[q]) {
                    sh_bin = bin;
                    sh_need = need - cum;
                }
                cum += c[q];
            }
        }
        __syncthreads();
        prefix |= ((unsigned long long)sh_bin) << shift;
        pmask  |= (255ull << shift);
        __syncthreads();
    }

    if (t == 0) g_thr[bh] = prefix;       // exactly the k-th largest key
}

// ---------------------------------------------------------------------------
// Kernel 3: 32-row tiles. Phase 1: coalesced key burst -> masks (+mask_out).
// Phase 2: stream rows, warp-uniform read-skip for masked-out heads.
// ---------------------------------------------------------------------------
__global__ void __launch_bounds__(256) filter_kernel(
    const float* __restrict__ x,
    float* __restrict__ xout,
    float* __restrict__ mask_out)     // may be null
{
    __shared__ float m[TILE_][H_];
    const int tile0 = blockIdx.x * TILE_;
    const int t = threadIdx.x;

    {
        const int rl = t >> 3;
        const int hd = t & 7;
        const int row = tile0 + rl;
        const int b = row >> 12;                 // F_ = 4096
        unsigned long long key = g_keys[(size_t)row * H_ + hd];
        float mv = (key >= g_thr[b * H_ + hd]) ? 1.0f : 0.0f;
        m[rl][hd] = mv;
        if (mask_out) mask_out[(size_t)row * H_ + hd] = mv;
    }
    __syncthreads();

    const int head = t >> 5;                      // warp-uniform head
#pragma unroll 4
    for (int r = 0; r < TILE_; r++) {
        const int row = tile0 + r;
        float4* __restrict__ xo = (float4*)(xout + (size_t)row * D_);
        if (m[r][head] != 0.0f) {
            const float4* __restrict__ xr = (const float4*)(x + (size_t)row * D_);
            xo[t] = xr[t];
        } else {
            xo[t] = make_float4(0.f, 0.f, 0.f, 0.f);
        }
    }
}

// ---------------------------------------------------------------------------
extern "C" void kernel_launch(void* const* d_in, const int* in_sizes, int n_in,
                              void* d_out, int out_size)
{
    const float* x    = (const float*)d_in[0];  // (B,F,D)
    const float* W    = (const float*)d_in[1];  // (D,H)
    const float* bias = (const float*)d_in[2];  // (H)
    const float* soff = (const float*)d_in[3];  // (H)

    const int nrows = in_sizes[0] / D_;         // B*F
    const int B = nrows / F_;

    float* xout = (float*)d_out;
    float* mask_out = nullptr;
    long long need = (long long)nrows * D_ + (long long)nrows * H_;
    if ((long long)out_size >= need)
        mask_out = (float*)d_out + (size_t)nrows * H_ * 0 + (size_t)nrows * D_;

    const int smem_bytes = (H_ * D_ + NS * STAGE_FLOATS) * sizeof(float); // 192KB
    static int attr_set = 0;
    if (!attr_set) {
        cudaFuncSetAttribute(score_kernel,
                             cudaFuncAttributeMaxDynamicSharedMemorySize, smem_bytes);
        attr_set = 1;
    }

    // 1) scores -> keys (cp.async 5-stage pipeline, persistent)
    score_kernel<<<148, 256, smem_bytes>>>(x, W, bias, nrows);
    // 2) exact per-(b,h) top-k threshold via radix-select
    topk_kernel<<<B * H_, 1024>>>(soff);
    // 3) mask + filtered output (32-row tiles)
    filter_kernel<<<nrows / TILE_, 256>>>(x, xout, mask_out);
}

// round 8
// speedup vs baseline: 1.7675x; 1.7675x over previous
#include <cuda_runtime.h>
#include <math.h>

#define D_ 1024
#define H_ 8
#define F_ 4096
#define R_ 5     // rows per warp in score kernel
#define TILE_ 32 // rows per filter block

// Scratch: keys [b][f][h] (64B per row), thresholds per (b,h).
__device__ unsigned long long g_keys[8 * 4096 * 8];
__device__ unsigned long long g_thr[64];

__device__ __forceinline__ unsigned int f2ord(float f) {
    unsigned int u = __float_as_uint(f);
    return (u & 0x80000000u) ? ~u : (u | 0x80000000u);
}
__device__ __forceinline__ unsigned long long pack2(float lo, float hi) {
    unsigned long long p;
    asm("mov.b64 %0, {%1, %2};" : "=l"(p) : "f"(lo), "f"(hi));
    return p;
}
__device__ __forceinline__ void unpack2(unsigned long long p, float& lo, float& hi) {
    asm("mov.b64 {%0, %1}, %2;" : "=f"(lo), "=f"(hi) : "l"(p));
}
#define FMA2(acc, a, b) \
    asm("fma.rn.f32x2 %0, %1, %2, %0;" : "+l"(acc) : "l"(a), "l"(b))

// ---------------------------------------------------------------------------
// Kernel 1: scores -> 64-bit keys, FFMA2, 5 rows/warp (round-6 structure),
// PLUS: streams zeros into xout for the same rows (fills idle write BW during
// load stalls; lets the filter kernel skip 70% of its writes).
// ---------------------------------------------------------------------------
__global__ void __launch_bounds__(256, 2) score_kernel(
    const float* __restrict__ x,
    const float* __restrict__ W,      // [D, H] row-major
    const float* __restrict__ bias,   // [H]
    float* __restrict__ xout,         // pre-zeroed here
    int nrows)                        // B*F
{
    __shared__ __align__(16) float Wt[H_][D_];   // 32 KB, transposed

    for (int i = threadIdx.x; i < D_ * H_; i += blockDim.x) {
        int d = i >> 3;
        int h = i & 7;
        Wt[h][d] = W[i];
    }
    __syncthreads();

    const int warp = threadIdx.x >> 5;
    const int lane = threadIdx.x & 31;
    const int totalWarps = gridDim.x * 8;
    const int nbatch = (nrows + R_ - 1) / R_;
    const unsigned long long ABS2 = 0x7FFFFFFF7FFFFFFFull;
    const float4 z4 = make_float4(0.f, 0.f, 0.f, 0.f);

    for (int batch = blockIdx.x * 8 + warp; batch < nbatch; batch += totalWarps) {
        const int row0 = batch * R_;
        const bool full = (row0 + R_ <= nrows);
        const float4* __restrict__ xr = (const float4*)(x + (size_t)row0 * D_);

        unsigned long long acc2[R_][H_];
#pragma unroll
        for (int r = 0; r < R_; r++)
#pragma unroll
            for (int h = 0; h < H_; h++) acc2[r][h] = 0ull;

#pragma unroll
        for (int j = 0; j < D_ / 128; j++) {
            const int d4 = lane + 32 * j;
            unsigned long long axy[R_], azw[R_];
#pragma unroll
            for (int r = 0; r < R_; r++) {
                float4 v;
                if (full || row0 + r < nrows) v = xr[r * (D_ / 4) + d4];
                else v = z4;
                axy[r] = pack2(v.x, v.y) & ABS2;   // |x|,|y| packed
                azw[r] = pack2(v.z, v.w) & ABS2;   // |z|,|w| packed
            }
#pragma unroll
            for (int h = 0; h < H_; h++) {
                const ulonglong2 wv = *(const ulonglong2*)&Wt[h][4 * d4];
#pragma unroll
                for (int r = 0; r < R_; r++) {
                    FMA2(acc2[r][h], axy[r], wv.x);
                    FMA2(acc2[r][h], azw[r], wv.y);
                }
            }
        }

        // Stream zeros for these rows into xout (fire-and-forget stores).
#pragma unroll
        for (int r = 0; r < R_; r++) {
            const int row = row0 + r;
            if (full || row < nrows) {
                float4* __restrict__ xo = (float4*)(xout + (size_t)row * D_);
#pragma unroll
                for (int q = 0; q < 8; q++)
                    __stcs(&xo[lane + 32 * q], z4);
            }
        }

        // Collapse packed halves, then butterfly reduce
        float acc[R_][H_];
#pragma unroll
        for (int r = 0; r < R_; r++)
#pragma unroll
            for (int h = 0; h < H_; h++) {
                float lo, hi;
                unpack2(acc2[r][h], lo, hi);
                acc[r][h] = lo + hi;
            }

#pragma unroll
        for (int off = 16; off; off >>= 1) {
#pragma unroll
            for (int r = 0; r < R_; r++)
#pragma unroll
                for (int h = 0; h < H_; h++)
                    acc[r][h] += __shfl_xor_sync(0xffffffffu, acc[r][h], off);
        }

        if (lane < R_) {
            const int r = lane;
            const int row = row0 + r;
            if (row < nrows) {
                const int b = row / F_;
                const int f = row - b * F_;
                const unsigned int finv = 0xFFFFFFFFu - (unsigned int)f; // tie -> lower f
                unsigned long long* __restrict__ kout = g_keys + (size_t)row * H_;
#pragma unroll
                for (int h = 0; h < H_; h++) {
                    float s = acc[r][h] + bias[h];
                    kout[h] = ((unsigned long long)f2ord(s) << 32) | (unsigned long long)finv;
                }
            }
        }
    }
}

// ---------------------------------------------------------------------------
// Kernel 2: per (b,h) exact radix-select (k-th largest of 4096 keys),
// 4-way split histograms to cut smem-atomic serialization.
// ---------------------------------------------------------------------------
__global__ void __launch_bounds__(1024) topk_kernel(
    const float* __restrict__ sparsity_offset)
{
    __shared__ unsigned long long s[F_];   // 32 KB
    __shared__ int hist[4][256];
    __shared__ int sh_bin, sh_need;

    const int bh = blockIdx.x;
    const int b  = bh >> 3;
    const int h  = bh & (H_ - 1);
    const int t  = threadIdx.x;
    const int lane = t & 31;
    const int wg4 = (t >> 5) & 3;

#pragma unroll
    for (int j = 0; j < 4; j++) {
        int i = t + j * 1024;
        s[i] = g_keys[((size_t)b * F_ + i) * H_ + h];
    }

    if (t == 0) {
        double off = (double)sparsity_offset[h];
        double sp  = 1.0 / (1.0 + exp(-off)) * 0.3 + 0.15;
        int k = (int)((double)F_ * sp);     // trunc, matches numpy int()
        if (k < 1)  k = 1;
        if (k > F_) k = F_;
        sh_need = k;
    }
    __syncthreads();

    unsigned long long prefix = 0ull, pmask = 0ull;

    for (int shift = 56; shift >= 0; shift -= 8) {
        if (t < 256) { hist[0][t] = 0; hist[1][t] = 0; hist[2][t] = 0; hist[3][t] = 0; }
        __syncthreads();
#pragma unroll
        for (int j = 0; j < 4; j++) {
            unsigned long long key = s[t + j * 1024];
            if ((key & pmask) == prefix)
                atomicAdd(&hist[wg4][(int)((key >> shift) & 255ull)], 1);
        }
        __syncthreads();

        if (t < 32) {
            int c[8], lsum = 0;
#pragma unroll
            for (int q = 0; q < 8; q++) {
                int bin = lane * 8 + q;
                c[q] = hist[0][bin] + hist[1][bin] + hist[2][bin] + hist[3][bin];
                lsum += c[q];
            }
            int ssum = lsum;
#pragma unroll
            for (int off = 1; off < 32; off <<= 1) {
                int o = __shfl_down_sync(0xffffffffu, ssum, off);
                if (lane + off < 32) ssum += o;
            }
            int above = ssum - lsum;
            int need = sh_need;
            int cum = above;
#pragma unroll
            for (int q = 7; q >= 0; q--) {
                int bin = lane * 8 + q;
                if (cum < need && need <= cum + c[q]) {
                    sh_bin = bin;
                    sh_need = need - cum;
                }
                cum += c[q];
            }
        }
        __syncthreads();
        prefix |= ((unsigned long long)sh_bin) << shift;
        pmask  |= (255ull << shift);
        __syncthreads();
    }

    if (t == 0) g_thr[bh] = prefix;       // exactly the k-th largest key
}

// ---------------------------------------------------------------------------
// Kernel 3: 32-row tiles. Phase 1: coalesced key burst -> masks (+mask_out).
// Phase 2: ONLY copy kept heads (xout already zeroed by score_kernel);
// masked-out heads do nothing at all.
// ---------------------------------------------------------------------------
__global__ void __launch_bounds__(256) filter_kernel(
    const float* __restrict__ x,
    float* __restrict__ xout,
    float* __restrict__ mask_out)     // may be null
{
    __shared__ float m[TILE_][H_];
    const int tile0 = blockIdx.x * TILE_;
    const int t = threadIdx.x;

    {
        const int rl = t >> 3;
        const int hd = t & 7;
        const int row = tile0 + rl;
        const int b = row >> 12;                 // F_ = 4096
        unsigned long long key = g_keys[(size_t)row * H_ + hd];
        float mv = (key >= g_thr[b * H_ + hd]) ? 1.0f : 0.0f;
        m[rl][hd] = mv;
        if (mask_out) mask_out[(size_t)row * H_ + hd] = mv;
    }
    __syncthreads();

    const int head = t >> 5;                      // warp-uniform head
#pragma unroll 4
    for (int r = 0; r < TILE_; r++) {
        if (m[r][head] != 0.0f) {
            const int row = tile0 + r;
            const float4* __restrict__ xr = (const float4*)(x + (size_t)row * D_);
            float4* __restrict__ xo = (float4*)(xout + (size_t)row * D_);
            xo[t] = xr[t];
        }
    }
}

// ---------------------------------------------------------------------------
extern "C" void kernel_launch(void* const* d_in, const int* in_sizes, int n_in,
                              void* d_out, int out_size)
{
    const float* x    = (const float*)d_in[0];  // (B,F,D)
    const float* W    = (const float*)d_in[1];  // (D,H)
    const float* bias = (const float*)d_in[2];  // (H)
    const float* soff = (const float*)d_in[3];  // (H)

    const int nrows = in_sizes[0] / D_;         // B*F
    const int B = nrows / F_;

    float* xout = (float*)d_out;
    float* mask_out = nullptr;
    long long need = (long long)nrows * D_ + (long long)nrows * H_;
    if ((long long)out_size >= need)
        mask_out = (float*)d_out + (size_t)nrows * D_;

    // 1) scores -> keys + zero-fill xout (overlaps writes with score's load stalls)
    score_kernel<<<296, 256>>>(x, W, bias, xout, nrows);
    // 2) exact per-(b,h) top-k threshold via radix-select
    topk_kernel<<<B * H_, 1024>>>(soff);
    // 3) mask + copy kept heads only
    filter_kernel<<<nrows / TILE_, 256>>>(x, xout, mask_out);
}

// round 9
// speedup vs baseline: 1.8734x; 1.0599x over previous
#include <cuda_runtime.h>
#include <cuda_pipeline.h>
#include <math.h>

#define D_ 1024
#define H_ 8
#define F_ 4096
#define TILE_ 32     // rows per filter block
#define SR 8         // rows per score stage (per warp batch)
#define SCHUNK 256   // floats per row per stage chunk (1KB)
#define STG_FLOATS (SR * SCHUNK)   // 2048 floats = 8KB per stage

// Scratch: keys [b][f][h] (64B per row), thresholds per (b,h).
__device__ unsigned long long g_keys[8 * 4096 * 8];
__device__ unsigned long long g_thr[64];

__device__ __forceinline__ unsigned int f2ord(float f) {
    unsigned int u = __float_as_uint(f);
    return (u & 0x80000000u) ? ~u : (u | 0x80000000u);
}
__device__ __forceinline__ unsigned long long pack2(float lo, float hi) {
    unsigned long long p;
    asm("mov.b64 %0, {%1, %2};" : "=l"(p) : "f"(lo), "f"(hi));
    return p;
}
__device__ __forceinline__ void unpack2(unsigned long long p, float& lo, float& hi) {
    asm("mov.b64 {%0, %1}, %2;" : "=f"(lo), "=f"(hi) : "l"(p));
}
__device__ __forceinline__ unsigned long long shfl_xor64(unsigned long long v, int off) {
    unsigned int lo = __shfl_xor_sync(0xffffffffu, (unsigned int)v, off);
    unsigned int hi = __shfl_xor_sync(0xffffffffu, (unsigned int)(v >> 32), off);
    return ((unsigned long long)hi << 32) | lo;
}
#define FMA2(acc, a, b) \
    asm("fma.rn.f32x2 %0, %1, %2, %0;" : "+l"(acc) : "l"(a), "l"(b))
#define ADD2(acc, a) \
    asm("add.rn.f32x2 %0, %0, %1;" : "+l"(acc) : "l"(a))

// Issue one stage's cp.async copies: 8 rows x 1KB chunk, lane-owns-column.
__device__ __forceinline__ void issue_stage(
    const float* __restrict__ x, float* dst,
    int batch, int c, int lane)
{
    const float* src = x + (size_t)batch * SR * D_ + c * SCHUNK;
#pragma unroll
    for (int r = 0; r < SR; r++)
#pragma unroll
        for (int q = 0; q < 2; q++)
            __pipeline_memcpy_async(dst + r * SCHUNK + (lane + 32 * q) * 4,
                                    src + (size_t)r * D_ + (lane + 32 * q) * 4, 16);
    __pipeline_commit();
}

// ---------------------------------------------------------------------------
// Kernel 1: warp-private cp.async double-buffered score. Each warp streams
// batches of 8 rows through 2 private 8KB smem stages; loads for stage m+1
// are in flight during compute of stage m. Each thread reads ONLY smem
// columns it copied itself -> no syncs in the main loop.
// ---------------------------------------------------------------------------
__global__ void __launch_bounds__(256, 1) score_kernel(
    const float* __restrict__ x,
    const float* __restrict__ W,      // [D, H]
    const float* __restrict__ bias,   // [H]
    int nrows)
{
    extern __shared__ float smem[];
    float* Wt  = smem;                          // [h*D_ + d], 32KB
    float* stg = smem + H_ * D_;                // 8 warps * 2 stages * 8KB

    const int tid  = threadIdx.x;
    const int warp = tid >> 5;
    const int lane = tid & 31;
    const int bid  = blockIdx.x;
    const int grid = gridDim.x;

    for (int i = tid; i < D_ * H_; i += 256) {
        int d = i >> 3, h = i & 7;
        Wt[h * D_ + d] = W[i];
    }
    __syncthreads();

    // lane -> final (r,h) ownership after multi-value reduce (5-bit bit-reversal)
    const int j0 = __brev((unsigned)lane) >> 27;
    const int h0 = j0 & 7;
    const int rA = j0 >> 3;             // value 0: row rA, value 1: row rA+4
    const float bias_h = bias[h0];

    const int nbatch = nrows / SR;      // nrows divisible by 8
    const int gw = bid * 8 + warp;      // global warp id
    const int nwarps = grid * 8;
    const int my_n = (nbatch > gw) ? ((nbatch - gw + nwarps - 1) / nwarps) : 0;
    const int total_m = my_n * 4;       // 4 chunks per batch
    if (total_m == 0) return;

    float* buf = stg + warp * 2 * STG_FLOATS;
    const unsigned long long ABS2 = 0x7FFFFFFF7FFFFFFFull;

    // prologue
    issue_stage(x, buf, gw, 0, lane);

    unsigned long long acc[64];         // [r*8+h] packed f32x2

    for (int m = 0; m < total_m; m++) {
        const int c = m & 3;
        const int batch = gw + (m >> 2) * nwarps;

        if (m + 1 < total_m) {
            const int m1 = m + 1;
            issue_stage(x, buf + (m1 & 1) * STG_FLOATS,
                        gw + (m1 >> 2) * nwarps, m1 & 3, lane);
            __pipeline_wait_prior(1);
        } else {
            __pipeline_wait_prior(0);
        }

        if (c == 0) {
#pragma unroll
            for (int j = 0; j < 64; j++) acc[j] = 0ull;
        }

        const float4* bp = (const float4*)(buf + (m & 1) * STG_FLOATS);
#pragma unroll
        for (int j2 = 0; j2 < 2; j2++) {
            const int d4l = lane + 32 * j2;
            unsigned long long axy[SR], azw[SR];
#pragma unroll
            for (int r = 0; r < SR; r++) {
                float4 v = bp[r * (SCHUNK / 4) + d4l];
                axy[r] = pack2(v.x, v.y) & ABS2;
                azw[r] = pack2(v.z, v.w) & ABS2;
            }
            const int dg = c * SCHUNK + 4 * d4l;
#pragma unroll
            for (int h = 0; h < H_; h++) {
                const ulonglong2 wv = *(const ulonglong2*)&Wt[h * D_ + dg];
#pragma unroll
                for (int r = 0; r < SR; r++) {
                    FMA2(acc[r * 8 + h], axy[r], wv.x);
                    FMA2(acc[r * 8 + h], azw[r], wv.y);
                }
            }
        }

        if (c == 3) {
            // multi-value tree reduce: 64 -> 2 values, count halves per step
            int n = 64;
#pragma unroll
            for (int off = 16; off >= 1; off >>= 1) {
#pragma unroll
                for (int i = 0; i < 32; i++) {
                    if (i < n / 2) {
                        unsigned long long xx = acc[2 * i], yy = acc[2 * i + 1];
                        unsigned long long t = (lane & off) ? xx : yy;
                        t = shfl_xor64(t, off);
                        unsigned long long keep = (lane & off) ? yy : xx;
                        ADD2(keep, t);
                        acc[i] = keep;
                    }
                }
                n >>= 1;
            }
            // lane owns full sums for (rA, h0) and (rA+4, h0)
            const int row0 = batch * SR;
#pragma unroll
            for (int i = 0; i < 2; i++) {
                const int row = row0 + rA + 4 * i;
                float lo, hi;
                unpack2(acc[i], lo, hi);
                float s = lo + hi + bias_h;
                const int b = row / F_;
                const int f = row - b * F_;
                const unsigned int finv = 0xFFFFFFFFu - (unsigned int)f;
                g_keys[(size_t)row * H_ + h0] =
                    ((unsigned long long)f2ord(s) << 32) | (unsigned long long)finv;
            }
        }
    }
}

// ---------------------------------------------------------------------------
// Kernel 2: per (b,h) exact radix-select (k-th largest of 4096 keys),
// 4-way split histograms.
// ---------------------------------------------------------------------------
__global__ void __launch_bounds__(1024) topk_kernel(
    const float* __restrict__ sparsity_offset)
{
    __shared__ unsigned long long s[F_];   // 32 KB
    __shared__ int hist[4][256];
    __shared__ int sh_bin, sh_need;

    const int bh = blockIdx.x;
    const int b  = bh >> 3;
    const int h  = bh & (H_ - 1);
    const int t  = threadIdx.x;
    const int lane = t & 31;
    const int wg4 = (t >> 5) & 3;

#pragma unroll
    for (int j = 0; j < 4; j++) {
        int i = t + j * 1024;
        s[i] = g_keys[((size_t)b * F_ + i) * H_ + h];
    }

    if (t == 0) {
        double off = (double)sparsity_offset[h];
        double sp  = 1.0 / (1.0 + exp(-off)) * 0.3 + 0.15;
        int k = (int)((double)F_ * sp);     // trunc, matches numpy int()
        if (k < 1)  k = 1;
        if (k > F_) k = F_;
        sh_need = k;
    }
    __syncthreads();

    unsigned long long prefix = 0ull, pmask = 0ull;

    for (int shift = 56; shift >= 0; shift -= 8) {
        if (t < 256) { hist[0][t] = 0; hist[1][t] = 0; hist[2][t] = 0; hist[3][t] = 0; }
        __syncthreads();
#pragma unroll
        for (int j = 0; j < 4; j++) {
            unsigned long long key = s[t + j * 1024];
            if ((key & pmask) == prefix)
                atomicAdd(&hist[wg4][(int)((key >> shift) & 255ull)], 1);
        }
        __syncthreads();

        if (t < 32) {
            int c[8], lsum = 0;
#pragma unroll
            for (int q = 0; q < 8; q++) {
                int bin = lane * 8 + q;
                c[q] = hist[0][bin] + hist[1][bin] + hist[2][bin] + hist[3][bin];
                lsum += c[q];
            }
            int ssum = lsum;
#pragma unroll
            for (int off = 1; off < 32; off <<= 1) {
                int o = __shfl_down_sync(0xffffffffu, ssum, off);
                if (lane + off < 32) ssum += o;
            }
            int above = ssum - lsum;
            int need = sh_need;
            int cum = above;
#pragma unroll
            for (int q = 7; q >= 0; q--) {
                int bin = lane * 8 + q;
                if (cum < need && need <= cum + c[q]) {
                    sh_bin = bin;
                    sh_need = need - cum;
                }
                cum += c[q];
            }
        }
        __syncthreads();
        prefix |= ((unsigned long long)sh_bin) << shift;
        pmask  |= (255ull << shift);
        __syncthreads();
    }

    if (t == 0) g_thr[bh] = prefix;       // exactly the k-th largest key
}

// ---------------------------------------------------------------------------
// Kernel 3: 32-row tiles. Phase 1: coalesced key burst -> masks (+mask_out).
// Phase 2: write all rows (zeros for masked heads), read-skip masked heads.
// ---------------------------------------------------------------------------
__global__ void __launch_bounds__(256) filter_kernel(
    const float* __restrict__ x,
    float* __restrict__ xout,
    float* __restrict__ mask_out)     // may be null
{
    __shared__ float m[TILE_][H_];
    const int tile0 = blockIdx.x * TILE_;
    const int t = threadIdx.x;

    {
        const int rl = t >> 3;
        const int hd = t & 7;
        const int row = tile0 + rl;
        const int b = row >> 12;                 // F_ = 4096
        unsigned long long key = g_keys[(size_t)row * H_ + hd];
        float mv = (key >= g_thr[b * H_ + hd]) ? 1.0f : 0.0f;
        m[rl][hd] = mv;
        if (mask_out) mask_out[(size_t)row * H_ + hd] = mv;
    }
    __syncthreads();

    const int head = t >> 5;                      // warp-uniform head
#pragma unroll 4
    for (int r = 0; r < TILE_; r++) {
        const int row = tile0 + r;
        float4* __restrict__ xo = (float4*)(xout + (size_t)row * D_);
        if (m[r][head] != 0.0f) {
            const float4* __restrict__ xr = (const float4*)(x + (size_t)row * D_);
            xo[t] = xr[t];
        } else {
            xo[t] = make_float4(0.f, 0.f, 0.f, 0.f);
        }
    }
}

// ---------------------------------------------------------------------------
extern "C" void kernel_launch(void* const* d_in, const int* in_sizes, int n_in,
                              void* d_out, int out_size)
{
    const float* x    = (const float*)d_in[0];  // (B,F,D)
    const float* W    = (const float*)d_in[1];  // (D,H)
    const float* bias = (const float*)d_in[2];  // (H)
    const float* soff = (const float*)d_in[3];  // (H)

    const int nrows = in_sizes[0] / D_;         // B*F
    const int B = nrows / F_;

    float* xout = (float*)d_out;
    float* mask_out = nullptr;
    long long need = (long long)nrows * D_ + (long long)nrows * H_;
    if ((long long)out_size >= need)
        mask_out = (float*)d_out + (size_t)nrows * D_;

    const int smem_bytes = (H_ * D_ + 8 * 2 * STG_FLOATS) * sizeof(float); // 160KB
    static int attr_set = 0;
    if (!attr_set) {
        cudaFuncSetAttribute(score_kernel,
                             cudaFuncAttributeMaxDynamicSharedMemorySize, smem_bytes);
        attr_set = 1;
    }

    // 1) scores -> keys (warp-private cp.async double-buffered pipeline)
    score_kernel<<<148, 256, smem_bytes>>>(x, W, bias, nrows);
    // 2) exact per-(b,h) top-k threshold via radix-select
    topk_kernel<<<B * H_, 1024>>>(soff);
    // 3) mask + filtered output (32-row tiles, read-skip on masked heads)
    filter_kernel<<<nrows / TILE_, 256>>>(x, xout, mask_out);
}

// round 10
// speedup vs baseline: 1.9138x; 1.0216x over previous
#include <cuda_runtime.h>
#include <cuda_pipeline.h>
#include <math.h>

#define D_ 1024
#define H_ 8
#define F_ 4096
#define TILE_ 32     // rows per filter block
#define SR 8         // rows per score stage (per warp batch)
#define SCHUNK 256   // floats per row per stage chunk (1KB)
#define NSTG 3       // pipeline stages per warp
#define STG_FLOATS (SR * SCHUNK)   // 2048 floats = 8KB per stage

// Scratch: keys [b][f][h] (64B per row), thresholds per (b,h).
__device__ unsigned long long g_keys[8 * 4096 * 8];
__device__ unsigned long long g_thr[64];

__device__ __forceinline__ unsigned int f2ord(float f) {
    unsigned int u = __float_as_uint(f);
    return (u & 0x80000000u) ? ~u : (u | 0x80000000u);
}
__device__ __forceinline__ unsigned long long pack2(float lo, float hi) {
    unsigned long long p;
    asm("mov.b64 %0, {%1, %2};" : "=l"(p) : "f"(lo), "f"(hi));
    return p;
}
__device__ __forceinline__ void unpack2(unsigned long long p, float& lo, float& hi) {
    asm("mov.b64 {%0, %1}, %2;" : "=f"(lo), "=f"(hi) : "l"(p));
}
__device__ __forceinline__ unsigned long long shfl_xor64(unsigned long long v, int off) {
    unsigned int lo = __shfl_xor_sync(0xffffffffu, (unsigned int)v, off);
    unsigned int hi = __shfl_xor_sync(0xffffffffu, (unsigned int)(v >> 32), off);
    return ((unsigned long long)hi << 32) | lo;
}
#define FMA2(acc, a, b) \
    asm("fma.rn.f32x2 %0, %1, %2, %0;" : "+l"(acc) : "l"(a), "l"(b))
#define ADD2(acc, a) \
    asm("add.rn.f32x2 %0, %0, %1;" : "+l"(acc) : "l"(a))

// Issue one stage's cp.async copies: 8 rows x 1KB chunk, lane-owns-column.
__device__ __forceinline__ void issue_stage(
    const float* __restrict__ x, float* dst,
    int batch, int c, int lane)
{
    const float* src = x + (size_t)batch * SR * D_ + c * SCHUNK;
#pragma unroll
    for (int r = 0; r < SR; r++)
#pragma unroll
        for (int q = 0; q < 2; q++)
            __pipeline_memcpy_async(dst + r * SCHUNK + (lane + 32 * q) * 4,
                                    src + (size_t)r * D_ + (lane + 32 * q) * 4, 16);
}

// ---------------------------------------------------------------------------
// Kernel 1: warp-private cp.async TRIPLE-buffered score. Two 8KB groups per
// warp always in flight during compute. Each thread reads only smem columns
// it copied itself -> no syncs in the main loop.
// ---------------------------------------------------------------------------
__global__ void __launch_bounds__(256, 1) score_kernel(
    const float* __restrict__ x,
    const float* __restrict__ W,      // [D, H]
    const float* __restrict__ bias,   // [H]
    int nrows)
{
    extern __shared__ float smem[];
    float* Wt  = smem;                          // [h*D_ + d], 32KB
    float* stg = smem + H_ * D_;                // 8 warps * NSTG stages * 8KB

    const int tid  = threadIdx.x;
    const int warp = tid >> 5;
    const int lane = tid & 31;
    const int bid  = blockIdx.x;
    const int grid = gridDim.x;

    for (int i = tid; i < D_ * H_; i += 256) {
        int d = i >> 3, h = i & 7;
        Wt[h * D_ + d] = W[i];
    }
    __syncthreads();

    // lane -> final (r,h) ownership after multi-value reduce (5-bit bit-reversal)
    const int j0 = __brev((unsigned)lane) >> 27;
    const int h0 = j0 & 7;
    const int rA = j0 >> 3;             // value 0: row rA, value 1: row rA+4
    const float bias_h = bias[h0];

    const int nbatch = nrows / SR;      // nrows divisible by 8
    const int gw = bid * 8 + warp;      // global warp id
    const int nwarps = grid * 8;
    const int my_n = (nbatch > gw) ? ((nbatch - gw + nwarps - 1) / nwarps) : 0;
    const int total_m = my_n * 4;       // 4 chunks per batch
    if (total_m == 0) return;

    float* buf = stg + warp * NSTG * STG_FLOATS;
    const unsigned long long ABS2 = 0x7FFFFFFF7FFFFFFFull;

    // prologue: groups 0 and 1
    issue_stage(x, buf, gw, 0, lane);
    __pipeline_commit();
    if (total_m > 1)
        issue_stage(x, buf + STG_FLOATS, gw + ((1 >> 2) * nwarps), 1 & 3, lane);
    __pipeline_commit();

    unsigned long long acc[64];         // [r*8+h] packed f32x2

    for (int m = 0; m < total_m; m++) {
        const int c = m & 3;
        const int batch = gw + (m >> 2) * nwarps;

        // issue group m+2 (empty commit past the end keeps group accounting uniform)
        {
            const int mi = m + 2;
            if (mi < total_m)
                issue_stage(x, buf + (mi % NSTG) * STG_FLOATS,
                            gw + (mi >> 2) * nwarps, mi & 3, lane);
            __pipeline_commit();
        }
        __pipeline_wait_prior(2);       // group m complete; m+1, m+2 in flight

        if (c == 0) {
#pragma unroll
            for (int j = 0; j < 64; j++) acc[j] = 0ull;
        }

        const float4* bp = (const float4*)(buf + (m % NSTG) * STG_FLOATS);
#pragma unroll
        for (int j2 = 0; j2 < 2; j2++) {
            const int d4l = lane + 32 * j2;
            unsigned long long axy[SR], azw[SR];
#pragma unroll
            for (int r = 0; r < SR; r++) {
                float4 v = bp[r * (SCHUNK / 4) + d4l];
                axy[r] = pack2(v.x, v.y) & ABS2;
                azw[r] = pack2(v.z, v.w) & ABS2;
            }
            const int dg = c * SCHUNK + 4 * d4l;
#pragma unroll
            for (int h = 0; h < H_; h++) {
                const ulonglong2 wv = *(const ulonglong2*)&Wt[h * D_ + dg];
#pragma unroll
                for (int r = 0; r < SR; r++) {
                    FMA2(acc[r * 8 + h], axy[r], wv.x);
                    FMA2(acc[r * 8 + h], azw[r], wv.y);
                }
            }
        }

        if (c == 3) {
            // multi-value tree reduce: 64 -> 2 values, count halves per step
            int n = 64;
#pragma unroll
            for (int off = 16; off >= 1; off >>= 1) {
#pragma unroll
                for (int i = 0; i < 32; i++) {
                    if (i < n / 2) {
                        unsigned long long xx = acc[2 * i], yy = acc[2 * i + 1];
                        unsigned long long t = (lane & off) ? xx : yy;
                        t = shfl_xor64(t, off);
                        unsigned long long keep = (lane & off) ? yy : xx;
                        ADD2(keep, t);
                        acc[i] = keep;
                    }
                }
                n >>= 1;
            }
            // lane owns full sums for (rA, h0) and (rA+4, h0)
            const int row0 = batch * SR;
#pragma unroll
            for (int i = 0; i < 2; i++) {
                const int row = row0 + rA + 4 * i;
                float lo, hi;
                unpack2(acc[i], lo, hi);
                float s = lo + hi + bias_h;
                const int b = row / F_;
                const int f = row - b * F_;
                const unsigned int finv = 0xFFFFFFFFu - (unsigned int)f;
                g_keys[(size_t)row * H_ + h0] =
                    ((unsigned long long)f2ord(s) << 32) | (unsigned long long)finv;
            }
        }
    }
}

// ---------------------------------------------------------------------------
// Kernel 2: per (b,h) exact radix-select (k-th largest of 4096 keys),
// 4-way split histograms.
// ---------------------------------------------------------------------------
__global__ void __launch_bounds__(1024) topk_kernel(
    const float* __restrict__ sparsity_offset)
{
    __shared__ unsigned long long s[F_];   // 32 KB
    __shared__ int hist[4][256];
    __shared__ int sh_bin, sh_need;

    const int bh = blockIdx.x;
    const int b  = bh >> 3;
    const int h  = bh & (H_ - 1);
    const int t  = threadIdx.x;
    const int lane = t & 31;
    const int wg4 = (t >> 5) & 3;

#pragma unroll
    for (int j = 0; j < 4; j++) {
        int i = t + j * 1024;
        s[i] = g_keys[((size_t)b * F_ + i) * H_ + h];
    }

    if (t == 0) {
        double off = (double)sparsity_offset[h];
        double sp  = 1.0 / (1.0 + exp(-off)) * 0.3 + 0.15;
        int k = (int)((double)F_ * sp);     // trunc, matches numpy int()
        if (k < 1)  k = 1;
        if (k > F_) k = F_;
        sh_need = k;
    }
    __syncthreads();

    unsigned long long prefix = 0ull, pmask = 0ull;

    for (int shift = 56; shift >= 0; shift -= 8) {
        if (t < 256) { hist[0][t] = 0; hist[1][t] = 0; hist[2][t] = 0; hist[3][t] = 0; }
        __syncthreads();
#pragma unroll
        for (int j = 0; j < 4; j++) {
            unsigned long long key = s[t + j * 1024];
            if ((key & pmask) == prefix)
                atomicAdd(&hist[wg4][(int)((key >> shift) & 255ull)], 1);
        }
        __syncthreads();

        if (t < 32) {
            int c[8], lsum = 0;
#pragma unroll
            for (int q = 0; q < 8; q++) {
                int bin = lane * 8 + q;
                c[q] = hist[0][bin] + hist[1][bin] + hist[2][bin] + hist[3][bin];
                lsum += c[q];
            }
            int ssum = lsum;
#pragma unroll
            for (int off = 1; off < 32; off <<= 1) {
                int o = __shfl_down_sync(0xffffffffu, ssum, off);
                if (lane + off < 32) ssum += o;
            }
            int above = ssum - lsum;
            int need = sh_need;
            int cum = above;
#pragma unroll
            for (int q = 7; q >= 0; q--) {
                int bin = lane * 8 + q;
                if (cum < need && need <= cum + c[q]) {
                    sh_bin = bin;
                    sh_need = need - cum;
                }
                cum += c[q];
            }
        }
        __syncthreads();
        prefix |= ((unsigned long long)sh_bin) << shift;
        pmask  |= (255ull << shift);
        __syncthreads();
    }

    if (t == 0) g_thr[bh] = prefix;       // exactly the k-th largest key
}

// ---------------------------------------------------------------------------
// Kernel 3: 32-row tiles. Phase 1: coalesced key burst -> masks (+mask_out).
// Phase 2: streaming stores (.cs) for xout (never re-read -> don't pollute L2,
// keep x resident for the 30% copy reads); read-skip masked heads.
// ---------------------------------------------------------------------------
__global__ void __launch_bounds__(256) filter_kernel(
    const float* __restrict__ x,
    float* __restrict__ xout,
    float* __restrict__ mask_out)     // may be null
{
    __shared__ float m[TILE_][H_];
    const int tile0 = blockIdx.x * TILE_;
    const int t = threadIdx.x;

    {
        const int rl = t >> 3;
        const int hd = t & 7;
        const int row = tile0 + rl;
        const int b = row >> 12;                 // F_ = 4096
        unsigned long long key = g_keys[(size_t)row * H_ + hd];
        float mv = (key >= g_thr[b * H_ + hd]) ? 1.0f : 0.0f;
        m[rl][hd] = mv;
        if (mask_out) mask_out[(size_t)row * H_ + hd] = mv;
    }
    __syncthreads();

    const int head = t >> 5;                      // warp-uniform head
    const float4 z4 = make_float4(0.f, 0.f, 0.f, 0.f);
#pragma unroll 8
    for (int r = 0; r < TILE_; r++) {
        const int row = tile0 + r;
        float4* __restrict__ xo = (float4*)(xout + (size_t)row * D_);
        if (m[r][head] != 0.0f) {
            const float4* __restrict__ xr = (const float4*)(x + (size_t)row * D_);
            __stcs(&xo[t], xr[t]);
        } else {
            __stcs(&xo[t], z4);
        }
    }
}

// ---------------------------------------------------------------------------
extern "C" void kernel_launch(void* const* d_in, const int* in_sizes, int n_in,
                              void* d_out, int out_size)
{
    const float* x    = (const float*)d_in[0];  // (B,F,D)
    const float* W    = (const float*)d_in[1];  // (D,H)
    const float* bias = (const float*)d_in[2];  // (H)
    const float* soff = (const float*)d_in[3];  // (H)

    const int nrows = in_sizes[0] / D_;         // B*F
    const int B = nrows / F_;

    float* xout = (float*)d_out;
    float* mask_out = nullptr;
    long long need = (long long)nrows * D_ + (long long)nrows * H_;
    if ((long long)out_size >= need)
        mask_out = (float*)d_out + (size_t)nrows * D_;

    const int smem_bytes = (H_ * D_ + 8 * NSTG * STG_FLOATS) * sizeof(float); // 224KB
    static int attr_set = 0;
    if (!attr_set) {
        cudaFuncSetAttribute(score_kernel,
                             cudaFuncAttributeMaxDynamicSharedMemorySize, smem_bytes);
        attr_set = 1;
    }

    // 1) scores -> keys (warp-private cp.async triple-buffered pipeline)
    score_kernel<<<148, 256, smem_bytes>>>(x, W, bias, nrows);
    // 2) exact per-(b,h) top-k threshold via radix-select
    topk_kernel<<<B * H_, 1024>>>(soff);
    // 3) mask + filtered output (32-row tiles, streaming stores)
    filter_kernel<<<nrows / TILE_, 256>>>(x, xout, mask_out);
}

// round 11
// speedup vs baseline: 1.9146x; 1.0004x over previous
#include <cuda_runtime.h>
#include <cuda_pipeline.h>
#include <math.h>

#define D_ 1024
#define H_ 8
#define F_ 4096
#define TILE_ 32     // rows per filter block
#define SR 4         // rows per score stage
#define SCHUNK 256   // floats per row-chunk per stage (1KB)
#define NSTG 6       // pipeline stages per warp
#define STG_FLOATS (SR * SCHUNK)   // 1024 floats = 4KB per stage

// Scratch: keys [b][f][h] (64B per row), thresholds per (b,h).
__device__ unsigned long long g_keys[8 * 4096 * 8];
__device__ unsigned long long g_thr[64];

__device__ __forceinline__ unsigned int f2ord(float f) {
    unsigned int u = __float_as_uint(f);
    return (u & 0x80000000u) ? ~u : (u | 0x80000000u);
}
__device__ __forceinline__ unsigned long long pack2(float lo, float hi) {
    unsigned long long p;
    asm("mov.b64 %0, {%1, %2};" : "=l"(p) : "f"(lo), "f"(hi));
    return p;
}
__device__ __forceinline__ void unpack2(unsigned long long p, float& lo, float& hi) {
    asm("mov.b64 {%0, %1}, %2;" : "=f"(lo), "=f"(hi) : "l"(p));
}
__device__ __forceinline__ unsigned long long shfl_xor64(unsigned long long v, int off) {
    unsigned int lo = __shfl_xor_sync(0xffffffffu, (unsigned int)v, off);
    unsigned int hi = __shfl_xor_sync(0xffffffffu, (unsigned int)(v >> 32), off);
    return ((unsigned long long)hi << 32) | lo;
}
#define FMA2(acc, a, b) \
    asm("fma.rn.f32x2 %0, %1, %2, %0;" : "+l"(acc) : "l"(a), "l"(b))
#define ADD2(acc, a) \
    asm("add.rn.f32x2 %0, %0, %1;" : "+l"(acc) : "l"(a))

// Issue one stage: 4 rows x 1KB chunk, lane-owns-column (no sync needed).
__device__ __forceinline__ void issue_stage(
    const float* __restrict__ x, float* dst,
    int batch, int c, int lane)
{
    const float* src = x + (size_t)batch * SR * D_ + c * SCHUNK;
#pragma unroll
    for (int r = 0; r < SR; r++)
#pragma unroll
        for (int q = 0; q < 2; q++)
            __pipeline_memcpy_async(dst + r * SCHUNK + (lane + 32 * q) * 4,
                                    src + (size_t)r * D_ + (lane + 32 * q) * 4, 16);
}

// ---------------------------------------------------------------------------
// Kernel 1: warp-private cp.async 6-stage pipelined score. 4-row batches give
// near-perfect load balance (6.92 avg batches/warp -> 6 or 7). Each thread
// reads only smem columns it copied itself -> no syncs in the main loop.
// ---------------------------------------------------------------------------
__global__ void __launch_bounds__(256, 1) score_kernel(
    const float* __restrict__ x,
    const float* __restrict__ W,      // [D, H]
    const float* __restrict__ bias,   // [H]
    int nrows)
{
    extern __shared__ float smem[];
    float* Wt  = smem;                          // [h*D_ + d], 32KB
    float* stg = smem + H_ * D_;                // 8 warps * NSTG * 4KB

    const int tid  = threadIdx.x;
    const int warp = tid >> 5;
    const int lane = tid & 31;
    const int bid  = blockIdx.x;
    const int grid = gridDim.x;

    for (int i = tid; i < D_ * H_; i += 256) {
        int d = i >> 3, h = i & 7;
        Wt[h * D_ + d] = W[i];
    }
    __syncthreads();

    // lane -> final (r,h) ownership after tree reduce (5-bit bit-reversal)
    const int j0 = __brev((unsigned)lane) >> 27;   // 0..31
    const int h0 = j0 & 7;
    const int rA = j0 >> 3;                        // 0..3
    const float bias_h = bias[h0];

    const int nbatch = nrows / SR;
    const int gw = bid * 8 + warp;
    const int nwarps = grid * 8;
    const int my_n = (nbatch > gw) ? ((nbatch - gw + nwarps - 1) / nwarps) : 0;
    const int total_m = my_n * 4;       // 4 chunks per batch
    if (total_m == 0) return;

    float* buf = stg + warp * NSTG * STG_FLOATS;
    const unsigned long long ABS2 = 0x7FFFFFFF7FFFFFFFull;

    // prologue: NSTG-1 groups (uniform commit accounting)
#pragma unroll
    for (int i = 0; i < NSTG - 1; i++) {
        if (i < total_m)
            issue_stage(x, buf + (i % NSTG) * STG_FLOATS,
                        gw + (i >> 2) * nwarps, i & 3, lane);
        __pipeline_commit();
    }

    unsigned long long acc[32];         // [r*8+h] packed f32x2

    for (int m = 0; m < total_m; m++) {
        const int c = m & 3;
        const int batch = gw + (m >> 2) * nwarps;

        {
            const int mi = m + NSTG - 1;
            if (mi < total_m)
                issue_stage(x, buf + (mi % NSTG) * STG_FLOATS,
                            gw + (mi >> 2) * nwarps, mi & 3, lane);
            __pipeline_commit();
        }
        __pipeline_wait_prior(NSTG - 1);   // group m complete; NSTG-1 in flight

        if (c == 0) {
#pragma unroll
            for (int j = 0; j < 32; j++) acc[j] = 0ull;
        }

        const float4* bp = (const float4*)(buf + (m % NSTG) * STG_FLOATS);
#pragma unroll
        for (int j2 = 0; j2 < 2; j2++) {
            const int d4l = lane + 32 * j2;
            unsigned long long axy[SR], azw[SR];
#pragma unroll
            for (int r = 0; r < SR; r++) {
                float4 v = bp[r * (SCHUNK / 4) + d4l];
                axy[r] = pack2(v.x, v.y) & ABS2;
                azw[r] = pack2(v.z, v.w) & ABS2;
            }
            const int dg = c * SCHUNK + 4 * d4l;
#pragma unroll
            for (int h = 0; h < H_; h++) {
                const ulonglong2 wv = *(const ulonglong2*)&Wt[h * D_ + dg];
#pragma unroll
                for (int r = 0; r < SR; r++) {
                    FMA2(acc[r * 8 + h], axy[r], wv.x);
                    FMA2(acc[r * 8 + h], azw[r], wv.y);
                }
            }
        }

        if (c == 3) {
            // tree reduce: 32 values -> 1 per lane (count halves per step)
            int n = 32;
#pragma unroll
            for (int off = 16; off >= 1; off >>= 1) {
#pragma unroll
                for (int i = 0; i < 16; i++) {
                    if (i < n / 2) {
                        unsigned long long xx = acc[2 * i], yy = acc[2 * i + 1];
                        unsigned long long t = (lane & off) ? xx : yy;
                        t = shfl_xor64(t, off);
                        unsigned long long keep = (lane & off) ? yy : xx;
                        ADD2(keep, t);
                        acc[i] = keep;
                    }
                }
                n >>= 1;
            }
            // lane owns the full sum for (rA, h0)
            const int row = batch * SR + rA;
            float lo, hi;
            unpack2(acc[0], lo, hi);
            float s = lo + hi + bias_h;
            const int b = row / F_;
            const int f = row - b * F_;
            const unsigned int finv = 0xFFFFFFFFu - (unsigned int)f;
            g_keys[(size_t)row * H_ + h0] =
                ((unsigned long long)f2ord(s) << 32) | (unsigned long long)finv;
        }
    }
}

// ---------------------------------------------------------------------------
// Kernel 2: per (b,h) exact radix-select; ALSO writes the mask floats so the
// filter never touches the 17MB key array again.
// ---------------------------------------------------------------------------
__global__ void __launch_bounds__(1024) topk_kernel(
    const float* __restrict__ sparsity_offset,
    float* __restrict__ mask_out)     // may be null
{
    __shared__ unsigned long long s[F_];   // 32 KB
    __shared__ int hist[4][256];
    __shared__ int sh_bin, sh_need;

    const int bh = blockIdx.x;
    const int b  = bh >> 3;
    const int h  = bh & (H_ - 1);
    const int t  = threadIdx.x;
    const int lane = t & 31;
    const int wg4 = (t >> 5) & 3;

#pragma unroll
    for (int j = 0; j < 4; j++) {
        int i = t + j * 1024;
        s[i] = g_keys[((size_t)b * F_ + i) * H_ + h];
    }

    if (t == 0) {
        double off = (double)sparsity_offset[h];
        double sp  = 1.0 / (1.0 + exp(-off)) * 0.3 + 0.15;
        int k = (int)((double)F_ * sp);     // trunc, matches numpy int()
        if (k < 1)  k = 1;
        if (k > F_) k = F_;
        sh_need = k;
    }
    __syncthreads();

    unsigned long long prefix = 0ull, pmask = 0ull;

    for (int shift = 56; shift >= 0; shift -= 8) {
        if (t < 256) { hist[0][t] = 0; hist[1][t] = 0; hist[2][t] = 0; hist[3][t] = 0; }
        __syncthreads();
#pragma unroll
        for (int j = 0; j < 4; j++) {
            unsigned long long key = s[t + j * 1024];
            if ((key & pmask) == prefix)
                atomicAdd(&hist[wg4][(int)((key >> shift) & 255ull)], 1);
        }
        __syncthreads();

        if (t < 32) {
            int c[8], lsum = 0;
#pragma unroll
            for (int q = 0; q < 8; q++) {
                int bin = lane * 8 + q;
                c[q] = hist[0][bin] + hist[1][bin] + hist[2][bin] + hist[3][bin];
                lsum += c[q];
            }
            int ssum = lsum;
#pragma unroll
            for (int off = 1; off < 32; off <<= 1) {
                int o = __shfl_down_sync(0xffffffffu, ssum, off);
                if (lane + off < 32) ssum += o;
            }
            int above = ssum - lsum;
            int need = sh_need;
            int cum = above;
#pragma unroll
            for (int q = 7; q >= 0; q--) {
                int bin = lane * 8 + q;
                if (cum < need && need <= cum + c[q]) {
                    sh_bin = bin;
                    sh_need = need - cum;
                }
                cum += c[q];
            }
        }
        __syncthreads();
        prefix |= ((unsigned long long)sh_bin) << shift;
        pmask  |= (255ull << shift);
        __syncthreads();
    }

    if (t == 0) g_thr[bh] = prefix;       // k-th largest key

    // Emit mask for this (b,h): keys are distinct -> exactly k ones.
    if (mask_out) {
#pragma unroll
        for (int j = 0; j < 4; j++) {
            int i = t + j * 1024;
            mask_out[((size_t)b * F_ + i) * H_ + h] =
                (s[i] >= prefix) ? 1.0f : 0.0f;
        }
    }
}

// ---------------------------------------------------------------------------
// Kernel 3: 32-row tiles. Phase 1: 1KB coalesced mask read (written by topk;
// fallback = compute from keys if mask_out is null). Phase 2: streaming
// stores; read-skip masked heads (warp-uniform).
// ---------------------------------------------------------------------------
__global__ void __launch_bounds__(256) filter_kernel(
    const float* __restrict__ x,
    float* __restrict__ xout,
    const float* __restrict__ mask_in)   // null -> derive from keys
{
    __shared__ float m[TILE_][H_];
    const int tile0 = blockIdx.x * TILE_;
    const int t = threadIdx.x;

    if (mask_in) {
        m[t >> 3][t & 7] = mask_in[(size_t)tile0 * H_ + t];   // coalesced 1KB
    } else {
        const int rl = t >> 3;
        const int hd = t & 7;
        const int row = tile0 + rl;
        const int b = row >> 12;                 // F_ = 4096
        unsigned long long key = g_keys[(size_t)row * H_ + hd];
        m[rl][hd] = (key >= g_thr[b * H_ + hd]) ? 1.0f : 0.0f;
    }
    __syncthreads();

    const int head = t >> 5;                      // warp-uniform head
    const float4 z4 = make_float4(0.f, 0.f, 0.f, 0.f);
#pragma unroll 8
    for (int r = 0; r < TILE_; r++) {
        const int row = tile0 + r;
        float4* __restrict__ xo = (float4*)(xout + (size_t)row * D_);
        if (m[r][head] != 0.0f) {
            const float4* __restrict__ xr = (const float4*)(x + (size_t)row * D_);
            __stcs(&xo[t], xr[t]);
        } else {
            __stcs(&xo[t], z4);
        }
    }
}

// ---------------------------------------------------------------------------
extern "C" void kernel_launch(void* const* d_in, const int* in_sizes, int n_in,
                              void* d_out, int out_size)
{
    const float* x    = (const float*)d_in[0];  // (B,F,D)
    const float* W    = (const float*)d_in[1];  // (D,H)
    const float* bias = (const float*)d_in[2];  // (H)
    const float* soff = (const float*)d_in[3];  // (H)

    const int nrows = in_sizes[0] / D_;         // B*F
    const int B = nrows / F_;

    float* xout = (float*)d_out;
    float* mask_out = nullptr;
    long long need = (long long)nrows * D_ + (long long)nrows * H_;
    if ((long long)out_size >= need)
        mask_out = (float*)d_out + (size_t)nrows * D_;

    const int smem_bytes = (H_ * D_ + 8 * NSTG * STG_FLOATS) * sizeof(float); // 224KB
    static int attr_set = 0;
    if (!attr_set) {
        cudaFuncSetAttribute(score_kernel,
                             cudaFuncAttributeMaxDynamicSharedMemorySize, smem_bytes);
        attr_set = 1;
    }

    // 1) scores -> keys (warp-private cp.async 6-stage pipeline, 4-row batches)
    score_kernel<<<148, 256, smem_bytes>>>(x, W, bias, nrows);
    // 2) exact per-(b,h) top-k threshold + mask emission
    topk_kernel<<<B * H_, 1024>>>(soff, mask_out);
    // 3) filtered output (32-row tiles, streaming stores)
    filter_kernel<<<nrows / TILE_, 256>>>(x, xout, mask_out);
}

// round 12
// speedup vs baseline: 1.9179x; 1.0017x over previous
#include <cuda_runtime.h>
#include <cuda_pipeline.h>
#include <math.h>

#define D_ 1024
#define H_ 8
#define F_ 4096
#define TILE_ 32     // rows per filter block
#define SR 4         // rows per score stage
#define SCHUNK 256   // floats per row-chunk per stage (1KB)
#define NSTG 6       // pipeline stages per warp
#define STG_FLOATS (SR * SCHUNK)   // 1024 floats = 4KB per stage

// Scratch: keys [b][f][h], thresholds, mask in [bh][f] layout (coalesced).
__device__ unsigned long long g_keys[8 * 4096 * 8];
__device__ unsigned long long g_thr[64];
__device__ float g_mask[64 * 4096];

__device__ __forceinline__ unsigned int f2ord(float f) {
    unsigned int u = __float_as_uint(f);
    return (u & 0x80000000u) ? ~u : (u | 0x80000000u);
}
__device__ __forceinline__ unsigned long long pack2(float lo, float hi) {
    unsigned long long p;
    asm("mov.b64 %0, {%1, %2};" : "=l"(p) : "f"(lo), "f"(hi));
    return p;
}
__device__ __forceinline__ void unpack2(unsigned long long p, float& lo, float& hi) {
    asm("mov.b64 {%0, %1}, %2;" : "=f"(lo), "=f"(hi) : "l"(p));
}
__device__ __forceinline__ unsigned long long shfl_xor64(unsigned long long v, int off) {
    unsigned int lo = __shfl_xor_sync(0xffffffffu, (unsigned int)v, off);
    unsigned int hi = __shfl_xor_sync(0xffffffffu, (unsigned int)(v >> 32), off);
    return ((unsigned long long)hi << 32) | lo;
}
#define FMA2(acc, a, b) \
    asm("fma.rn.f32x2 %0, %1, %2, %0;" : "+l"(acc) : "l"(a), "l"(b))
#define ADD2(acc, a) \
    asm("add.rn.f32x2 %0, %0, %1;" : "+l"(acc) : "l"(a))

// Issue one stage: 4 rows x 1KB chunk, lane-owns-column (no sync needed).
__device__ __forceinline__ void issue_stage(
    const float* __restrict__ x, float* dst,
    int batch, int c, int lane)
{
    const float* src = x + (size_t)batch * SR * D_ + c * SCHUNK;
#pragma unroll
    for (int r = 0; r < SR; r++)
#pragma unroll
        for (int q = 0; q < 2; q++)
            __pipeline_memcpy_async(dst + r * SCHUNK + (lane + 32 * q) * 4,
                                    src + (size_t)r * D_ + (lane + 32 * q) * 4, 16);
}

// ---------------------------------------------------------------------------
// Kernel 1: warp-private cp.async 6-stage pipelined score. After consuming
// each chunk, the warp zero-fills the mirror 4KB of xout with streaming
// stores -- soaking the idle write bandwidth so the filter never writes zeros.
// ---------------------------------------------------------------------------
__global__ void __launch_bounds__(256, 1) score_kernel(
    const float* __restrict__ x,
    const float* __restrict__ W,      // [D, H]
    const float* __restrict__ bias,   // [H]
    float* __restrict__ xout,         // zero-filled here
    int nrows)
{
    extern __shared__ float smem[];
    float* Wt  = smem;                          // [h*D_ + d], 32KB
    float* stg = smem + H_ * D_;                // 8 warps * NSTG * 4KB

    const int tid  = threadIdx.x;
    const int warp = tid >> 5;
    const int lane = tid & 31;
    const int bid  = blockIdx.x;
    const int grid = gridDim.x;

    for (int i = tid; i < D_ * H_; i += 256) {
        int d = i >> 3, h = i & 7;
        Wt[h * D_ + d] = W[i];
    }
    __syncthreads();

    // lane -> final (r,h) ownership after tree reduce (5-bit bit-reversal)
    const int j0 = __brev((unsigned)lane) >> 27;   // 0..31
    const int h0 = j0 & 7;
    const int rA = j0 >> 3;                        // 0..3
    const float bias_h = bias[h0];

    const int nbatch = nrows / SR;
    const int gw = bid * 8 + warp;
    const int nwarps = grid * 8;
    const int my_n = (nbatch > gw) ? ((nbatch - gw + nwarps - 1) / nwarps) : 0;
    const int total_m = my_n * 4;       // 4 chunks per batch
    if (total_m == 0) return;

    float* buf = stg + warp * NSTG * STG_FLOATS;
    const unsigned long long ABS2 = 0x7FFFFFFF7FFFFFFFull;
    const float4 z4 = make_float4(0.f, 0.f, 0.f, 0.f);

    // prologue: NSTG-1 groups (uniform commit accounting)
#pragma unroll
    for (int i = 0; i < NSTG - 1; i++) {
        if (i < total_m)
            issue_stage(x, buf + (i % NSTG) * STG_FLOATS,
                        gw + (i >> 2) * nwarps, i & 3, lane);
        __pipeline_commit();
    }

    unsigned long long acc[32];         // [r*8+h] packed f32x2

    for (int m = 0; m < total_m; m++) {
        const int c = m & 3;
        const int batch = gw + (m >> 2) * nwarps;

        {
            const int mi = m + NSTG - 1;
            if (mi < total_m)
                issue_stage(x, buf + (mi % NSTG) * STG_FLOATS,
                            gw + (mi >> 2) * nwarps, mi & 3, lane);
            __pipeline_commit();
        }
        __pipeline_wait_prior(NSTG - 1);   // group m complete; NSTG-1 in flight

        if (c == 0) {
#pragma unroll
            for (int j = 0; j < 32; j++) acc[j] = 0ull;
        }

        const float4* bp = (const float4*)(buf + (m % NSTG) * STG_FLOATS);
#pragma unroll
        for (int j2 = 0; j2 < 2; j2++) {
            const int d4l = lane + 32 * j2;
            unsigned long long axy[SR], azw[SR];
#pragma unroll
            for (int r = 0; r < SR; r++) {
                float4 v = bp[r * (SCHUNK / 4) + d4l];
                axy[r] = pack2(v.x, v.y) & ABS2;
                azw[r] = pack2(v.z, v.w) & ABS2;
            }
            const int dg = c * SCHUNK + 4 * d4l;
#pragma unroll
            for (int h = 0; h < H_; h++) {
                const ulonglong2 wv = *(const ulonglong2*)&Wt[h * D_ + dg];
#pragma unroll
                for (int r = 0; r < SR; r++) {
                    FMA2(acc[r * 8 + h], axy[r], wv.x);
                    FMA2(acc[r * 8 + h], azw[r], wv.y);
                }
            }
        }

        // Zero-fill the mirror 4KB of xout (fire-and-forget streaming stores)
        {
            float* zo = xout + (size_t)batch * SR * D_ + c * SCHUNK;
#pragma unroll
            for (int r = 0; r < SR; r++)
#pragma unroll
                for (int q = 0; q < 2; q++)
                    __stcs((float4*)(zo + (size_t)r * D_ + (lane + 32 * q) * 4), z4);
        }

        if (c == 3) {
            // tree reduce: 32 values -> 1 per lane (count halves per step)
            int n = 32;
#pragma unroll
            for (int off = 16; off >= 1; off >>= 1) {
#pragma unroll
                for (int i = 0; i < 16; i++) {
                    if (i < n / 2) {
                        unsigned long long xx = acc[2 * i], yy = acc[2 * i + 1];
                        unsigned long long t = (lane & off) ? xx : yy;
                        t = shfl_xor64(t, off);
                        unsigned long long keep = (lane & off) ? yy : xx;
                        ADD2(keep, t);
                        acc[i] = keep;
                    }
                }
                n >>= 1;
            }
            // lane owns the full sum for (rA, h0)
            const int row = batch * SR + rA;
            float lo, hi;
            unpack2(acc[0], lo, hi);
            float s = lo + hi + bias_h;
            const int b = row / F_;
            const int f = row - b * F_;
            const unsigned int finv = 0xFFFFFFFFu - (unsigned int)f;
            g_keys[(size_t)row * H_ + h0] =
                ((unsigned long long)f2ord(s) << 32) | (unsigned long long)finv;
        }
    }
}

// ---------------------------------------------------------------------------
// Kernel 2: per (b,h) exact radix-select; writes mask to scratch in [bh][f]
// layout (fully coalesced 16KB per block).
// ---------------------------------------------------------------------------
__global__ void __launch_bounds__(1024) topk_kernel(
    const float* __restrict__ sparsity_offset)
{
    __shared__ unsigned long long s[F_];   // 32 KB
    __shared__ int hist[4][256];
    __shared__ int sh_bin, sh_need;

    const int bh = blockIdx.x;
    const int b  = bh >> 3;
    const int h  = bh & (H_ - 1);
    const int t  = threadIdx.x;
    const int lane = t & 31;
    const int wg4 = (t >> 5) & 3;

#pragma unroll
    for (int j = 0; j < 4; j++) {
        int i = t + j * 1024;
        s[i] = g_keys[((size_t)b * F_ + i) * H_ + h];
    }

    if (t == 0) {
        double off = (double)sparsity_offset[h];
        double sp  = 1.0 / (1.0 + exp(-off)) * 0.3 + 0.15;
        int k = (int)((double)F_ * sp);     // trunc, matches numpy int()
        if (k < 1)  k = 1;
        if (k > F_) k = F_;
        sh_need = k;
    }
    __syncthreads();

    unsigned long long prefix = 0ull, pmask = 0ull;

    for (int shift = 56; shift >= 0; shift -= 8) {
        if (t < 256) { hist[0][t] = 0; hist[1][t] = 0; hist[2][t] = 0; hist[3][t] = 0; }
        __syncthreads();
#pragma unroll
        for (int j = 0; j < 4; j++) {
            unsigned long long key = s[t + j * 1024];
            if ((key & pmask) == prefix)
                atomicAdd(&hist[wg4][(int)((key >> shift) & 255ull)], 1);
        }
        __syncthreads();

        if (t < 32) {
            int c[8], lsum = 0;
#pragma unroll
            for (int q = 0; q < 8; q++) {
                int bin = lane * 8 + q;
                c[q] = hist[0][bin] + hist[1][bin] + hist[2][bin] + hist[3][bin];
                lsum += c[q];
            }
            int ssum = lsum;
#pragma unroll
            for (int off = 1; off < 32; off <<= 1) {
                int o = __shfl_down_sync(0xffffffffu, ssum, off);
                if (lane + off < 32) ssum += o;
            }
            int above = ssum - lsum;
            int need = sh_need;
            int cum = above;
#pragma unroll
            for (int q = 7; q >= 0; q--) {
                int bin = lane * 8 + q;
                if (cum < need && need <= cum + c[q]) {
                    sh_bin = bin;
                    sh_need = need - cum;
                }
                cum += c[q];
            }
        }
        __syncthreads();
        prefix |= ((unsigned long long)sh_bin) << shift;
        pmask  |= (255ull << shift);
        __syncthreads();
    }

    if (t == 0) g_thr[bh] = prefix;       // k-th largest key

    // Emit mask in [bh][f] layout: coalesced, exactly k ones (keys distinct).
#pragma unroll
    for (int j = 0; j < 4; j++) {
        int i = t + j * 1024;
        g_mask[(size_t)bh * F_ + i] = (s[i] >= prefix) ? 1.0f : 0.0f;
    }
}

// ---------------------------------------------------------------------------
// Kernel 3: 32-row tiles. Reads 1KB of mask scratch, writes the d_out mask
// region coalesced, then copies ONLY kept heads (xout zeros already written
// by score_kernel).
// ---------------------------------------------------------------------------
__global__ void __launch_bounds__(256) filter_kernel(
    const float* __restrict__ x,
    float* __restrict__ xout,
    float* __restrict__ mask_out)     // may be null
{
    __shared__ float m[TILE_][H_];
    const int tile0 = blockIdx.x * TILE_;
    const int b = tile0 >> 12;                    // F_ = 4096
    const int f0 = tile0 & (F_ - 1);
    const int t = threadIdx.x;

    {   // load mask tile from scratch: head = t>>5, f = f0 + (t&31); coalesced
        const int h = t >> 5;
        const int f = f0 + (t & 31);
        m[t & 31][h] = g_mask[((size_t)(b * H_ + h)) * F_ + f];
    }
    __syncthreads();

    if (mask_out)   // coalesced 2KB burst: row = tile0 + (t>>3), head = t&7
        mask_out[(size_t)tile0 * H_ + t] = m[t >> 3][t & 7];

    const int head = t >> 5;                      // warp-uniform head
#pragma unroll 8
    for (int r = 0; r < TILE_; r++) {
        if (m[r][head] != 0.0f) {
            const int row = tile0 + r;
            const float4* __restrict__ xr = (const float4*)(x + (size_t)row * D_);
            float4* __restrict__ xo = (float4*)(xout + (size_t)row * D_);
            __stcs(&xo[t], xr[t]);
        }
    }
}

// ---------------------------------------------------------------------------
extern "C" void kernel_launch(void* const* d_in, const int* in_sizes, int n_in,
                              void* d_out, int out_size)
{
    const float* x    = (const float*)d_in[0];  // (B,F,D)
    const float* W    = (const float*)d_in[1];  // (D,H)
    const float* bias = (const float*)d_in[2];  // (H)
    const float* soff = (const float*)d_in[3];  // (H)

    const int nrows = in_sizes[0] / D_;         // B*F
    const int B = nrows / F_;

    float* xout = (float*)d_out;
    float* mask_out = nullptr;
    long long need = (long long)nrows * D_ + (long long)nrows * H_;
    if ((long long)out_size >= need)
        mask_out = (float*)d_out + (size_t)nrows * D_;

    const int smem_bytes = (H_ * D_ + 8 * NSTG * STG_FLOATS) * sizeof(float); // 224KB
    static int attr_set = 0;
    if (!attr_set) {
        cudaFuncSetAttribute(score_kernel,
                             cudaFuncAttributeMaxDynamicSharedMemorySize, smem_bytes);
        attr_set = 1;
    }

    // 1) scores -> keys + zero-fill xout (stores ride idle write BW)
    score_kernel<<<148, 256, smem_bytes>>>(x, W, bias, xout, nrows);
    // 2) exact per-(b,h) top-k threshold + coalesced mask scratch
    topk_kernel<<<B * H_, 1024>>>(soff);
    // 3) mask region + copy kept heads only
    filter_kernel<<<nrows / TILE_, 256>>>(x, xout, mask_out);
}